// round 1
// baseline (speedup 1.0000x reference)
#include <cuda_runtime.h>
#include <math.h>
#include <cstdint>

// Problem constants
#define BB 8
#define SS 2048
#define DD 1024
#define NEGC (-4294967295.0f)   // -(2^32) + 1

// Scratch (allocation-free rule: __device__ globals)
__device__ float g_q[(size_t)BB * SS * DD];      // 64 MB
__device__ float g_k[(size_t)BB * SS * DD];      // 64 MB
__device__ float g_v[(size_t)BB * SS * DD];      // 64 MB
__device__ float g_sc[(size_t)BB * SS * SS];     // 128 MB
__device__ float g_mask[(size_t)BB * SS];

// ---------------------------------------------------------------------------
// masks[b,s] = sin(|sum_d x[b,s,d]|)
// one block per row, 256 threads
// ---------------------------------------------------------------------------
__global__ __launch_bounds__(256) void mask_kernel(const float* __restrict__ x) {
    int row = blockIdx.x;                     // 0 .. B*S-1
    const float* xr = x + (size_t)row * DD;
    float s = 0.0f;
    for (int i = threadIdx.x; i < DD; i += 256) s += xr[i];
    #pragma unroll
    for (int o = 16; o > 0; o >>= 1) s += __shfl_xor_sync(0xffffffffu, s, o);
    __shared__ float ws[8];
    int w = threadIdx.x >> 5, l = threadIdx.x & 31;
    if (l == 0) ws[w] = s;
    __syncthreads();
    if (threadIdx.x == 0) {
        float t = 0.0f;
        #pragma unroll
        for (int i = 0; i < 8; i++) t += ws[i];
        // double-precision sin: robust even if harness compiles with fast-math
        g_mask[row] = (float)sin((double)fabsf(t));
    }
}

// ---------------------------------------------------------------------------
// Tiled GEMM: C[M,N] = A[M,K] * B   (B is [K,N] if !BT, [N,K] if BT)
// BM=BN=128, BK=16, 256 threads, 8x8 register tile per thread.
// EPI 0: relu(acc + bias[col])                 (aux = bias, stride sAux=0)
// EPI 1: acc * 1/32, key-masked to NEG         (aux = mask row for batch)
// EPI 2: acc + res[row,col]                    (res = q residual)
// blockIdx.z = batch; strides in elements.
// ---------------------------------------------------------------------------
template <int EPI, bool BT>
__global__ __launch_bounds__(256)
void gemm_kernel(const float* __restrict__ A, const float* __restrict__ Bp,
                 const float* __restrict__ aux, const float* __restrict__ res,
                 float* __restrict__ C,
                 int M, int N, int K,
                 long long sA, long long sB, long long sC, long long sAux)
{
    constexpr int BM = 128, BN = 128, BK = 16;
    __shared__ float As[BK][BM];
    __shared__ float Bs[BK][BN];

    const int bz = blockIdx.z;
    A  += (size_t)bz * sA;
    Bp += (size_t)bz * sB;
    C  += (size_t)bz * sC;
    if (EPI == 1) aux += (size_t)bz * sAux;
    if (EPI == 2) res += (size_t)bz * sC;

    const int row0 = blockIdx.y * BM;
    const int col0 = blockIdx.x * BN;

    const int tid = threadIdx.x;
    const int tx = tid & 15;      // 0..15 -> 8 cols each
    const int ty = tid >> 4;      // 0..15 -> 8 rows each

    float acc[8][8];
    #pragma unroll
    for (int i = 0; i < 8; i++)
        #pragma unroll
        for (int j = 0; j < 8; j++) acc[i][j] = 0.0f;

    for (int k0 = 0; k0 < K; k0 += BK) {
        // --- load A tile: 128x16, 512 float4, 2 per thread, store transposed
        #pragma unroll
        for (int it = 0; it < 2; it++) {
            int e = (tid + it * 256) * 4;
            int m = e >> 4;            // e / 16
            int k = e & 15;
            float4 va = *reinterpret_cast<const float4*>(
                &A[(size_t)(row0 + m) * K + k0 + k]);
            As[k + 0][m] = va.x; As[k + 1][m] = va.y;
            As[k + 2][m] = va.z; As[k + 3][m] = va.w;
        }
        // --- load B tile
        #pragma unroll
        for (int it = 0; it < 2; it++) {
            int e = (tid + it * 256) * 4;
            if (BT) {
                int n = e >> 4;
                int k = e & 15;
                float4 vb = *reinterpret_cast<const float4*>(
                    &Bp[(size_t)(col0 + n) * K + k0 + k]);
                Bs[k + 0][n] = vb.x; Bs[k + 1][n] = vb.y;
                Bs[k + 2][n] = vb.z; Bs[k + 3][n] = vb.w;
            } else {
                int k = e >> 7;        // e / 128
                int n = e & 127;
                *reinterpret_cast<float4*>(&Bs[k][n]) =
                    *reinterpret_cast<const float4*>(
                        &Bp[(size_t)(k0 + k) * N + col0 + n]);
            }
        }
        __syncthreads();

        #pragma unroll
        for (int k = 0; k < BK; k++) {
            float ra[8], rb[8];
            *reinterpret_cast<float4*>(ra)     = *reinterpret_cast<float4*>(&As[k][ty * 8]);
            *reinterpret_cast<float4*>(ra + 4) = *reinterpret_cast<float4*>(&As[k][ty * 8 + 4]);
            *reinterpret_cast<float4*>(rb)     = *reinterpret_cast<float4*>(&Bs[k][tx * 8]);
            *reinterpret_cast<float4*>(rb + 4) = *reinterpret_cast<float4*>(&Bs[k][tx * 8 + 4]);
            #pragma unroll
            for (int i = 0; i < 8; i++)
                #pragma unroll
                for (int j = 0; j < 8; j++)
                    acc[i][j] += ra[i] * rb[j];
        }
        __syncthreads();
    }

    // --- epilogue ---
    #pragma unroll
    for (int i = 0; i < 8; i++) {
        const int row = row0 + ty * 8 + i;
        #pragma unroll
        for (int j = 0; j < 8; j += 4) {
            const int col = col0 + tx * 8 + j;
            float4 v;
            v.x = acc[i][j]; v.y = acc[i][j + 1]; v.z = acc[i][j + 2]; v.w = acc[i][j + 3];
            if (EPI == 0) {
                v.x = fmaxf(v.x + aux[col + 0], 0.0f);
                v.y = fmaxf(v.y + aux[col + 1], 0.0f);
                v.z = fmaxf(v.z + aux[col + 2], 0.0f);
                v.w = fmaxf(v.w + aux[col + 3], 0.0f);
            } else if (EPI == 1) {
                const float sc = 0.03125f;   // 1/sqrt(1024)
                v.x = (aux[col + 0] == 0.0f) ? NEGC : v.x * sc;
                v.y = (aux[col + 1] == 0.0f) ? NEGC : v.y * sc;
                v.z = (aux[col + 2] == 0.0f) ? NEGC : v.z * sc;
                v.w = (aux[col + 3] == 0.0f) ? NEGC : v.w * sc;
            } else {
                float4 r = *reinterpret_cast<const float4*>(&res[(size_t)row * N + col]);
                v.x += r.x; v.y += r.y; v.z += r.z; v.w += r.w;
            }
            *reinterpret_cast<float4*>(&C[(size_t)row * N + col]) = v;
        }
    }
}

// ---------------------------------------------------------------------------
// In-place row softmax over S=2048 keys, then scale row by query mask.
// One block (256 threads) per (b, q) row.
// ---------------------------------------------------------------------------
__global__ __launch_bounds__(256) void softmax_kernel() {
    const int r  = blockIdx.x;       // 0..B*S-1
    const int b  = r >> 11;
    const int qi = r & 2047;
    float* srow = g_sc + (size_t)b * SS * SS + (size_t)qi * SS;
    const float mq = g_mask[r];

    const int t = threadIdx.x;
    float loc[8];
    #pragma unroll
    for (int i = 0; i < 8; i++) loc[i] = srow[t + i * 256];

    float m = loc[0];
    #pragma unroll
    for (int i = 1; i < 8; i++) m = fmaxf(m, loc[i]);
    #pragma unroll
    for (int o = 16; o > 0; o >>= 1) m = fmaxf(m, __shfl_xor_sync(0xffffffffu, m, o));

    __shared__ float red[8];
    const int w = t >> 5, l = t & 31;
    if (l == 0) red[w] = m;
    __syncthreads();
    float bm = red[0];
    #pragma unroll
    for (int i = 1; i < 8; i++) bm = fmaxf(bm, red[i]);
    __syncthreads();   // red about to be reused

    float s = 0.0f;
    #pragma unroll
    for (int i = 0; i < 8; i++) { loc[i] = expf(loc[i] - bm); s += loc[i]; }
    #pragma unroll
    for (int o = 16; o > 0; o >>= 1) s += __shfl_xor_sync(0xffffffffu, s, o);
    if (l == 0) red[w] = s;
    __syncthreads();
    float bs = 0.0f;
    #pragma unroll
    for (int i = 0; i < 8; i++) bs += red[i];

    const float inv = mq / bs;
    #pragma unroll
    for (int i = 0; i < 8; i++) srow[t + i * 256] = loc[i] * inv;
}

// ---------------------------------------------------------------------------
extern "C" void kernel_launch(void* const* d_in, const int* in_sizes, int n_in,
                              void* d_out, int out_size)
{
    const float* x  = (const float*)d_in[0];
    const float* Wq = (const float*)d_in[1];
    const float* bq = (const float*)d_in[2];
    const float* Wk = (const float*)d_in[3];
    const float* bk = (const float*)d_in[4];
    const float* Wv = (const float*)d_in[5];
    const float* bv = (const float*)d_in[6];
    float* out = (float*)d_out;

    float *q, *k, *v, *sc, *mask;
    cudaGetSymbolAddress((void**)&q,    g_q);
    cudaGetSymbolAddress((void**)&k,    g_k);
    cudaGetSymbolAddress((void**)&v,    g_v);
    cudaGetSymbolAddress((void**)&sc,   g_sc);
    cudaGetSymbolAddress((void**)&mask, g_mask);

    const int M  = BB * SS;         // 16384
    const dim3 blk(256);

    // 1) masks
    mask_kernel<<<M, blk>>>(x);

    // 2) QKV projections (M=16384, N=K=1024), relu + bias
    {
        dim3 grd(DD / 128, M / 128, 1);
        gemm_kernel<0, false><<<grd, blk>>>(x, Wq, bq, nullptr, q, M, DD, DD, 0, 0, 0, 0);
        gemm_kernel<0, false><<<grd, blk>>>(x, Wk, bk, nullptr, k, M, DD, DD, 0, 0, 0, 0);
        gemm_kernel<0, false><<<grd, blk>>>(x, Wv, bv, nullptr, v, M, DD, DD, 0, 0, 0, 0);
    }

    // 3) scores = q @ k^T / 32, key mask -> NEG   (batched over B)
    {
        dim3 grd(SS / 128, SS / 128, BB);
        gemm_kernel<1, true><<<grd, blk>>>(q, k, mask, nullptr, sc,
                                           SS, SS, DD,
                                           (long long)SS * DD, (long long)SS * DD,
                                           (long long)SS * SS, (long long)SS);
    }

    // 4) softmax + query-mask scaling (in place)
    softmax_kernel<<<M, blk>>>();

    // 5) out = attn @ v + q   (batched over B)
    {
        dim3 grd(DD / 128, SS / 128, BB);
        gemm_kernel<2, false><<<grd, blk>>>(sc, v, nullptr, q, out,
                                            SS, DD, SS,
                                            (long long)SS * SS, (long long)SS * DD,
                                            (long long)SS * DD, 0);
    }
}

// round 5
// speedup vs baseline: 3.2587x; 3.2587x over previous
#include <cuda_runtime.h>
#include <math.h>
#include <cstdint>

#define BB 8
#define SS 2048
#define DD 1024
#define NEGC (-4294967295.0f)   // -(2^32) + 1

// ---------------------------------------------------------------------------
// Scratch (__device__ globals: allocation-free rule)
// ---------------------------------------------------------------------------
__device__ float g_q [(size_t)BB * SS * DD];
__device__ float g_k [(size_t)BB * SS * DD];
__device__ float g_v [(size_t)BB * SS * DD];
__device__ float g_sc[(size_t)BB * SS * SS];
__device__ float g_mask[(size_t)BB * SS];

// ---------------------------------------------------------------------------
// PTX helpers (sm_80-compatible only; NO tcgen05 on plain sm_100 target)
// ---------------------------------------------------------------------------
__device__ __forceinline__ uint32_t smem_u32(const void* p) {
    uint32_t a;
    asm("{ .reg .u64 t; cvta.to.shared.u64 t, %1; cvt.u32.u64 %0, t; }" : "=r"(a) : "l"(p));
    return a;
}
#define CPA16(sa, gp) asm volatile("cp.async.cg.shared.global [%0], [%1], 16;" :: "r"(sa), "l"(gp))
#define CPA_COMMIT()  asm volatile("cp.async.commit_group;" ::: "memory")
template <int N>
__device__ __forceinline__ void cpa_wait() { asm volatile("cp.async.wait_group %0;" :: "n"(N) : "memory"); }

__device__ __forceinline__ uint32_t f2tf(float f) {
    uint32_t u;
    asm("cvt.rna.tf32.f32 %0, %1;" : "=r"(u) : "f"(f));
    return u;
}
__device__ __forceinline__ void mma_tf32(float* c, const uint32_t* a, const uint32_t* b) {
    asm volatile(
        "mma.sync.aligned.m16n8k8.row.col.f32.tf32.tf32.f32 "
        "{%0,%1,%2,%3}, {%4,%5,%6,%7}, {%8,%9}, {%0,%1,%2,%3};"
        : "+f"(c[0]), "+f"(c[1]), "+f"(c[2]), "+f"(c[3])
        : "r"(a[0]), "r"(a[1]), "r"(a[2]), "r"(a[3]), "r"(b[0]), "r"(b[1]));
}

// ---------------------------------------------------------------------------
// masks[b,s] = sin(|sum_d x|)
// ---------------------------------------------------------------------------
__global__ __launch_bounds__(256) void mask_kernel(const float* __restrict__ x) {
    int row = blockIdx.x;
    const float* xr = x + (size_t)row * DD;
    float s = 0.0f;
    for (int i = threadIdx.x; i < DD; i += 256) s += xr[i];
    #pragma unroll
    for (int o = 16; o > 0; o >>= 1) s += __shfl_xor_sync(0xffffffffu, s, o);
    __shared__ float ws[8];
    int w = threadIdx.x >> 5, l = threadIdx.x & 31;
    if (l == 0) ws[w] = s;
    __syncthreads();
    if (threadIdx.x == 0) {
        float t = 0.0f;
        #pragma unroll
        for (int i = 0; i < 8; i++) t += ws[i];
        g_mask[row] = (float)sin((double)fabsf(t));
    }
}

// ---------------------------------------------------------------------------
// Tensor-core tf32 GEMM.
//   C[M,N] = A[M,K] * B,   A row-major [M][K].
//   BLKN=0: B global is [N][K] row-major  (scores: B = k matrix)
//   BLKN=1: B global is [K][N] row-major  (proj: W; attn*v: v)
// Tiles: BM=BN=128, BK=32; 256 thr = 8 warps (2 x 4); warp tile 64x32.
// EPI 0: relu(acc + bias[col]); EPI 1: acc/32 + key mask; EPI 2: acc + res.
// ---------------------------------------------------------------------------
#define A_STRIDE 36            // floats per A smem row (BK=32 + 4 pad)
#define BNK_STRIDE 36          // B stored [n][k]
#define BKN_STRIDE 136         // B stored [k][n] (128 + 8 pad)
#define A_BYTES   (128 * A_STRIDE * 4)       // 18432
#define B_BYTES   18432                       // max(128*36, 32*136)*4
#define STAGE_BYTES (A_BYTES + B_BYTES)       // 36864
#define SMEM_TOTAL  (2 * STAGE_BYTES)         // 73728

__device__ __forceinline__ void load_A(uint32_t sa, const float* __restrict__ g,
                                       int ld, int tid) {
    // 128 rows x 32 floats: 1024 x 16B chunks, 4 per thread
    #pragma unroll
    for (int i = 0; i < 4; i++) {
        int idx = tid + i * 256;
        int row = idx >> 3, c = idx & 7;
        CPA16(sa + (uint32_t)(row * A_STRIDE + c * 4) * 4, g + (size_t)row * ld + c * 4);
    }
}
__device__ __forceinline__ void load_B_nk(uint32_t sb, const float* __restrict__ g,
                                          int ld, int tid) {
    #pragma unroll
    for (int i = 0; i < 4; i++) {
        int idx = tid + i * 256;
        int row = idx >> 3, c = idx & 7;
        CPA16(sb + (uint32_t)(row * BNK_STRIDE + c * 4) * 4, g + (size_t)row * ld + c * 4);
    }
}
__device__ __forceinline__ void load_B_kn(uint32_t sb, const float* __restrict__ g,
                                          int ld, int tid) {
    // 32 rows(k) x 128 floats: 1024 x 16B chunks, 4 per thread
    #pragma unroll
    for (int i = 0; i < 4; i++) {
        int idx = tid + i * 256;
        int row = idx >> 5, c = idx & 31;
        CPA16(sb + (uint32_t)(row * BKN_STRIDE + c * 4) * 4, g + (size_t)row * ld + c * 4);
    }
}

template <int EPI, int BLKN>
__global__ __launch_bounds__(256, 2)
void tc_gemm(const float* __restrict__ A, const float* __restrict__ B,
             const float* __restrict__ aux, const float* __restrict__ res,
             float* __restrict__ C,
             int ldA, int ldB, int ldC, int KITER,
             long long sA, long long sB, long long sC, long long sAux, long long sRes)
{
    extern __shared__ char smem[];
    const uint32_t sb0 = smem_u32(smem);
    const int tid = threadIdx.x;
    const int wid = tid >> 5, lane = tid & 31;
    const int r4 = lane >> 2, c4 = lane & 3;
    const int wm = wid >> 2, wn = wid & 3;       // 2 x 4 warp grid
    const int m0w = wm * 64, n0w = wn * 32;

    const int bz = blockIdx.z;
    A += (size_t)bz * sA;
    B += (size_t)bz * sB;
    C += (size_t)bz * sC;
    if (EPI == 1) aux += (size_t)bz * sAux;
    if (EPI == 2) res += (size_t)bz * sRes;

    const int row0 = blockIdx.y * 128;
    const int col0 = blockIdx.x * 128;

    const float* Ab = A + (size_t)row0 * ldA;                 // k offset added per iter
    const float* Bb = BLKN ? (B + col0)                        // [K][N]: advance rows per iter
                           : (B + (size_t)col0 * ldB);         // [N][K]: k offset per iter

    float acc[4][4][4];
    #pragma unroll
    for (int i = 0; i < 4; i++)
        #pragma unroll
        for (int j = 0; j < 4; j++)
            #pragma unroll
            for (int t = 0; t < 4; t++) acc[i][j][t] = 0.0f;

    // prefetch stage 0
    load_A(sb0, Ab, ldA, tid);
    if (BLKN) load_B_kn(sb0 + A_BYTES, Bb, ldB, tid);
    else      load_B_nk(sb0 + A_BYTES, Bb, ldB, tid);
    CPA_COMMIT();

    for (int it = 0; it < KITER; it++) {
        if (it + 1 < KITER) {
            uint32_t sn = sb0 + ((it + 1) & 1) * STAGE_BYTES;
            load_A(sn, Ab + (it + 1) * 32, ldA, tid);
            if (BLKN) load_B_kn(sn + A_BYTES, Bb + (size_t)(it + 1) * 32 * ldB, ldB, tid);
            else      load_B_nk(sn + A_BYTES, Bb + (it + 1) * 32, ldB, tid);
            CPA_COMMIT();
            cpa_wait<1>();
        } else {
            cpa_wait<0>();
        }
        __syncthreads();

        const float* As = (const float*)(smem + (it & 1) * STAGE_BYTES);
        const float* Bs = (const float*)(smem + (it & 1) * STAGE_BYTES + A_BYTES);

        #pragma unroll
        for (int kk = 0; kk < 32; kk += 8) {
            uint32_t a[4][4], b[4][2];
            const float* ap = As + (m0w + r4) * A_STRIDE + kk + c4;
            #pragma unroll
            for (int mt = 0; mt < 4; mt++) {
                a[mt][0] = f2tf(ap[mt * 16 * A_STRIDE]);
                a[mt][1] = f2tf(ap[mt * 16 * A_STRIDE + 8 * A_STRIDE]);
                a[mt][2] = f2tf(ap[mt * 16 * A_STRIDE + 4]);
                a[mt][3] = f2tf(ap[mt * 16 * A_STRIDE + 8 * A_STRIDE + 4]);
            }
            if (BLKN) {
                const float* bp = Bs + (kk + c4) * BKN_STRIDE + n0w + r4;
                #pragma unroll
                for (int nt = 0; nt < 4; nt++) {
                    b[nt][0] = f2tf(bp[nt * 8]);
                    b[nt][1] = f2tf(bp[4 * BKN_STRIDE + nt * 8]);
                }
            } else {
                const float* bp = Bs + (n0w + r4) * BNK_STRIDE + kk + c4;
                #pragma unroll
                for (int nt = 0; nt < 4; nt++) {
                    b[nt][0] = f2tf(bp[nt * 8 * BNK_STRIDE]);
                    b[nt][1] = f2tf(bp[nt * 8 * BNK_STRIDE + 4]);
                }
            }
            #pragma unroll
            for (int mt = 0; mt < 4; mt++)
                #pragma unroll
                for (int nt = 0; nt < 4; nt++)
                    mma_tf32(acc[mt][nt], a[mt], b[nt]);
        }
        __syncthreads();
    }

    // ---- epilogue ----
    #pragma unroll
    for (int mt = 0; mt < 4; mt++) {
        const int r0 = row0 + m0w + mt * 16 + r4;
        #pragma unroll
        for (int nt = 0; nt < 4; nt++) {
            const int col = col0 + n0w + nt * 8 + c4 * 2;
            float2 lo = make_float2(acc[mt][nt][0], acc[mt][nt][1]);   // row r0
            float2 hi = make_float2(acc[mt][nt][2], acc[mt][nt][3]);   // row r0+8
            if (EPI == 0) {
                float b0 = aux[col], b1 = aux[col + 1];
                lo.x = fmaxf(lo.x + b0, 0.0f); lo.y = fmaxf(lo.y + b1, 0.0f);
                hi.x = fmaxf(hi.x + b0, 0.0f); hi.y = fmaxf(hi.y + b1, 0.0f);
            } else if (EPI == 1) {
                float m0 = aux[col], m1 = aux[col + 1];
                lo.x = (m0 == 0.0f) ? NEGC : lo.x * 0.03125f;
                lo.y = (m1 == 0.0f) ? NEGC : lo.y * 0.03125f;
                hi.x = (m0 == 0.0f) ? NEGC : hi.x * 0.03125f;
                hi.y = (m1 == 0.0f) ? NEGC : hi.y * 0.03125f;
            } else {
                float2 rl = *reinterpret_cast<const float2*>(&res[(size_t)r0 * ldC + col]);
                float2 rh = *reinterpret_cast<const float2*>(&res[(size_t)(r0 + 8) * ldC + col]);
                lo.x += rl.x; lo.y += rl.y;
                hi.x += rh.x; hi.y += rh.y;
            }
            *reinterpret_cast<float2*>(&C[(size_t)r0 * ldC + col]) = lo;
            *reinterpret_cast<float2*>(&C[(size_t)(r0 + 8) * ldC + col]) = hi;
        }
    }
}

// ---------------------------------------------------------------------------
// softmax + query-mask (in place on g_sc)
// ---------------------------------------------------------------------------
__global__ __launch_bounds__(256) void softmax_kernel() {
    const int r = blockIdx.x;
    const int b = r >> 11, qi = r & 2047;
    float* srow = g_sc + (size_t)b * SS * SS + (size_t)qi * SS;
    const float mq = g_mask[r];
    const int t = threadIdx.x;
    float loc[8];
    #pragma unroll
    for (int i = 0; i < 8; i++) loc[i] = srow[t + i * 256];
    float m = loc[0];
    #pragma unroll
    for (int i = 1; i < 8; i++) m = fmaxf(m, loc[i]);
    #pragma unroll
    for (int o = 16; o > 0; o >>= 1) m = fmaxf(m, __shfl_xor_sync(0xffffffffu, m, o));
    __shared__ float red[8];
    const int w = t >> 5, l = t & 31;
    if (l == 0) red[w] = m;
    __syncthreads();
    float bm = red[0];
    #pragma unroll
    for (int i = 1; i < 8; i++) bm = fmaxf(bm, red[i]);
    __syncthreads();
    float s = 0.0f;
    #pragma unroll
    for (int i = 0; i < 8; i++) { loc[i] = expf(loc[i] - bm); s += loc[i]; }
    #pragma unroll
    for (int o = 16; o > 0; o >>= 1) s += __shfl_xor_sync(0xffffffffu, s, o);
    if (l == 0) red[w] = s;
    __syncthreads();
    float bs = 0.0f;
    #pragma unroll
    for (int i = 0; i < 8; i++) bs += red[i];
    const float inv = mq / bs;
    #pragma unroll
    for (int i = 0; i < 8; i++) srow[t + i * 256] = loc[i] * inv;
}

// ---------------------------------------------------------------------------
extern "C" void kernel_launch(void* const* d_in, const int* in_sizes, int n_in,
                              void* d_out, int out_size)
{
    const float* x  = (const float*)d_in[0];
    const float* Wq = (const float*)d_in[1];
    const float* bq = (const float*)d_in[2];
    const float* Wk = (const float*)d_in[3];
    const float* bk = (const float*)d_in[4];
    const float* Wv = (const float*)d_in[5];
    const float* bv = (const float*)d_in[6];
    float* out = (float*)d_out;

    float *q, *k, *v, *sc, *mask;
    cudaGetSymbolAddress((void**)&q,    g_q);
    cudaGetSymbolAddress((void**)&k,    g_k);
    cudaGetSymbolAddress((void**)&v,    g_v);
    cudaGetSymbolAddress((void**)&sc,   g_sc);
    cudaGetSymbolAddress((void**)&mask, g_mask);

    cudaFuncSetAttribute(tc_gemm<0, 1>, cudaFuncAttributeMaxDynamicSharedMemorySize, SMEM_TOTAL);
    cudaFuncSetAttribute(tc_gemm<1, 0>, cudaFuncAttributeMaxDynamicSharedMemorySize, SMEM_TOTAL);
    cudaFuncSetAttribute(tc_gemm<2, 1>, cudaFuncAttributeMaxDynamicSharedMemorySize, SMEM_TOTAL);

    const int M = BB * SS;                    // 16384
    const long long SD  = (long long)SS * DD;
    const long long SS2 = (long long)SS * SS;

    // 1) masks
    mask_kernel<<<M, 256>>>(x);

    // 2) QKV projections: q = relu(x @ W + b); B = W is [K=D][N=D]
    {
        dim3 grd(DD / 128, M / 128, 1);
        tc_gemm<0, 1><<<grd, 256, SMEM_TOTAL>>>(x, Wq, bq, nullptr, q,
                                                DD, DD, DD, DD / 32, 0, 0, 0, 0, 0);
        tc_gemm<0, 1><<<grd, 256, SMEM_TOTAL>>>(x, Wk, bk, nullptr, k,
                                                DD, DD, DD, DD / 32, 0, 0, 0, 0, 0);
        tc_gemm<0, 1><<<grd, 256, SMEM_TOTAL>>>(x, Wv, bv, nullptr, v,
                                                DD, DD, DD, DD / 32, 0, 0, 0, 0, 0);
    }

    // 3) scores = q @ k^T / 32, key mask; B = k matrix is [N=S][K=D]
    {
        dim3 grd(SS / 128, SS / 128, BB);
        tc_gemm<1, 0><<<grd, 256, SMEM_TOTAL>>>(q, k, mask, nullptr, sc,
                                                DD, DD, SS, DD / 32,
                                                SD, SD, SS2, SS, 0);
    }

    // 4) softmax + query mask
    softmax_kernel<<<M, 256>>>();

    // 5) out = attn @ v + q; B = v is [K=S][N=D]
    {
        dim3 grd(DD / 128, SS / 128, BB);
        tc_gemm<2, 1><<<grd, 256, SMEM_TOTAL>>>(sc, v, nullptr, q, out,
                                                SS, DD, DD, SS / 32,
                                                SS2, SD, SD, 0, SD);
    }
}

// round 6
// speedup vs baseline: 3.4539x; 1.0599x over previous
#include <cuda_runtime.h>
#include <math.h>
#include <cstdint>

#define BB 8
#define SS 2048
#define DD 1024
#define NEGC (-4294967295.0f)   // -(2^32) + 1

// ---------------------------------------------------------------------------
// Scratch (__device__ globals: allocation-free rule)
// ---------------------------------------------------------------------------
__device__ float g_x [(size_t)BB * SS * DD];     // tf32-rounded x
__device__ float g_w [(size_t)3 * DD * DD];      // tf32-rounded Wq|Wk|Wv
__device__ float g_q [(size_t)BB * SS * DD];     // tf32-rounded q (also residual)
__device__ float g_k [(size_t)BB * SS * DD];
__device__ float g_v [(size_t)BB * SS * DD];
__device__ float g_sc[(size_t)BB * SS * SS];
__device__ float g_mask[(size_t)BB * SS];

// ---------------------------------------------------------------------------
// PTX helpers (sm_80-compatible; NO tcgen05 on plain sm_100 target)
// ---------------------------------------------------------------------------
#define CPA16(sa, gp) asm volatile("cp.async.cg.shared.global [%0], [%1], 16;" :: "r"(sa), "l"(gp))
#define CPA_COMMIT()  asm volatile("cp.async.commit_group;" ::: "memory")
template <int N>
__device__ __forceinline__ void cpa_wait() { asm volatile("cp.async.wait_group %0;" :: "n"(N) : "memory"); }

__device__ __forceinline__ uint32_t smem_u32(const void* p) {
    uint32_t a;
    asm("{ .reg .u64 t; cvta.to.shared.u64 t, %1; cvt.u32.u64 %0, t; }" : "=r"(a) : "l"(p));
    return a;
}
__device__ __forceinline__ float f2tf_f(float f) {
    uint32_t u;
    asm("cvt.rna.tf32.f32 %0, %1;" : "=r"(u) : "f"(f));
    return __uint_as_float(u);
}
__device__ __forceinline__ void mma_tf32(float* c, const uint32_t* a, const uint32_t* b) {
    asm volatile(
        "mma.sync.aligned.m16n8k8.row.col.f32.tf32.tf32.f32 "
        "{%0,%1,%2,%3}, {%4,%5,%6,%7}, {%8,%9}, {%0,%1,%2,%3};"
        : "+f"(c[0]), "+f"(c[1]), "+f"(c[2]), "+f"(c[3])
        : "r"(a[0]), "r"(a[1]), "r"(a[2]), "r"(a[3]), "r"(b[0]), "r"(b[1]));
}

// ---------------------------------------------------------------------------
// tf32 pre-rounding pass (float4 vectorized)
// ---------------------------------------------------------------------------
__global__ __launch_bounds__(256) void cvt_tf32_kernel(const float* __restrict__ src,
                                                       float* __restrict__ dst, int n4) {
    int i = blockIdx.x * 256 + threadIdx.x;
    int stride = gridDim.x * 256;
    for (; i < n4; i += stride) {
        float4 v = reinterpret_cast<const float4*>(src)[i];
        v.x = f2tf_f(v.x); v.y = f2tf_f(v.y);
        v.z = f2tf_f(v.z); v.w = f2tf_f(v.w);
        reinterpret_cast<float4*>(dst)[i] = v;
    }
}

// ---------------------------------------------------------------------------
// masks[b,s] = sin(|sum_d x|)  (reads original fp32 x for exactness)
// ---------------------------------------------------------------------------
__global__ __launch_bounds__(256) void mask_kernel(const float* __restrict__ x) {
    int row = blockIdx.x;
    const float* xr = x + (size_t)row * DD;
    float s = 0.0f;
    for (int i = threadIdx.x; i < DD; i += 256) s += xr[i];
    #pragma unroll
    for (int o = 16; o > 0; o >>= 1) s += __shfl_xor_sync(0xffffffffu, s, o);
    __shared__ float ws[8];
    int w = threadIdx.x >> 5, l = threadIdx.x & 31;
    if (l == 0) ws[w] = s;
    __syncthreads();
    if (threadIdx.x == 0) {
        float t = 0.0f;
        #pragma unroll
        for (int i = 0; i < 8; i++) t += ws[i];
        g_mask[row] = (float)sin((double)fabsf(t));
    }
}

// ---------------------------------------------------------------------------
// Tensor-core tf32 GEMM; all operands PRE-ROUNDED to tf32 in global memory,
// so the mainloop is pure LDS + MMA (no cvt).
//   BLKN=0: B global [N][K];  BLKN=1: B global [K][N]
// BM=BN=128, BK=32; 256 thr = 8 warps (2x4); warp tile 64x32.
// EPI 0: tf32(relu(acc+bias)); EPI 1: acc/32 + key mask; EPI 2: acc + res.
// ---------------------------------------------------------------------------
#define A_STRIDE 36
#define BNK_STRIDE 36
#define BKN_STRIDE 136
#define A_BYTES   (128 * A_STRIDE * 4)
#define B_BYTES   18432
#define STAGE_BYTES (A_BYTES + B_BYTES)
#define SMEM_TOTAL  (2 * STAGE_BYTES)

__device__ __forceinline__ void load_A(uint32_t sa, const float* __restrict__ g,
                                       int ld, int tid) {
    #pragma unroll
    for (int i = 0; i < 4; i++) {
        int idx = tid + i * 256;
        int row = idx >> 3, c = idx & 7;
        CPA16(sa + (uint32_t)(row * A_STRIDE + c * 4) * 4, g + (size_t)row * ld + c * 4);
    }
}
__device__ __forceinline__ void load_B_nk(uint32_t sb, const float* __restrict__ g,
                                          int ld, int tid) {
    #pragma unroll
    for (int i = 0; i < 4; i++) {
        int idx = tid + i * 256;
        int row = idx >> 3, c = idx & 7;
        CPA16(sb + (uint32_t)(row * BNK_STRIDE + c * 4) * 4, g + (size_t)row * ld + c * 4);
    }
}
__device__ __forceinline__ void load_B_kn(uint32_t sb, const float* __restrict__ g,
                                          int ld, int tid) {
    #pragma unroll
    for (int i = 0; i < 4; i++) {
        int idx = tid + i * 256;
        int row = idx >> 5, c = idx & 31;
        CPA16(sb + (uint32_t)(row * BKN_STRIDE + c * 4) * 4, g + (size_t)row * ld + c * 4);
    }
}

template <int EPI, int BLKN>
__global__ __launch_bounds__(256, 2)
void tc_gemm(const float* __restrict__ A, const float* __restrict__ B,
             const float* __restrict__ aux, const float* __restrict__ res,
             float* __restrict__ C,
             int ldA, int ldB, int ldC, int KITER,
             long long sA, long long sB, long long sC, long long sAux, long long sRes)
{
    extern __shared__ char smem[];
    const uint32_t sb0 = smem_u32(smem);
    const int tid = threadIdx.x;
    const int wid = tid >> 5, lane = tid & 31;
    const int r4 = lane >> 2, c4 = lane & 3;
    const int wm = wid >> 2, wn = wid & 3;
    const int m0w = wm * 64, n0w = wn * 32;

    const int bz = blockIdx.z;
    A += (size_t)bz * sA;
    B += (size_t)bz * sB;
    C += (size_t)bz * sC;
    if (EPI == 1) aux += (size_t)bz * sAux;
    if (EPI == 2) res += (size_t)bz * sRes;

    const int row0 = blockIdx.y * 128;
    const int col0 = blockIdx.x * 128;

    const float* Ab = A + (size_t)row0 * ldA;
    const float* Bb = BLKN ? (B + col0) : (B + (size_t)col0 * ldB);

    float acc[4][4][4];
    #pragma unroll
    for (int i = 0; i < 4; i++)
        #pragma unroll
        for (int j = 0; j < 4; j++)
            #pragma unroll
            for (int t = 0; t < 4; t++) acc[i][j][t] = 0.0f;

    load_A(sb0, Ab, ldA, tid);
    if (BLKN) load_B_kn(sb0 + A_BYTES, Bb, ldB, tid);
    else      load_B_nk(sb0 + A_BYTES, Bb, ldB, tid);
    CPA_COMMIT();

    for (int it = 0; it < KITER; it++) {
        if (it + 1 < KITER) {
            uint32_t sn = sb0 + ((it + 1) & 1) * STAGE_BYTES;
            load_A(sn, Ab + (it + 1) * 32, ldA, tid);
            if (BLKN) load_B_kn(sn + A_BYTES, Bb + (size_t)(it + 1) * 32 * ldB, ldB, tid);
            else      load_B_nk(sn + A_BYTES, Bb + (it + 1) * 32, ldB, tid);
            CPA_COMMIT();
            cpa_wait<1>();
        } else {
            cpa_wait<0>();
        }
        __syncthreads();

        const uint32_t* As = (const uint32_t*)(smem + (it & 1) * STAGE_BYTES);
        const uint32_t* Bs = (const uint32_t*)(smem + (it & 1) * STAGE_BYTES + A_BYTES);

        // hoisted fragment base pointers (data pre-rounded: no cvt in loop)
        const uint32_t* apb = As + (m0w + r4) * A_STRIDE + c4;
        const uint32_t* bpb_kn = Bs + c4 * BKN_STRIDE + n0w + r4;
        const uint32_t* bpb_nk = Bs + (n0w + r4) * BNK_STRIDE + c4;

        #pragma unroll
        for (int kk = 0; kk < 32; kk += 8) {
            uint32_t a[4][4], b[4][2];
            const uint32_t* ap = apb + kk;
            #pragma unroll
            for (int mt = 0; mt < 4; mt++) {
                a[mt][0] = ap[mt * 16 * A_STRIDE];
                a[mt][1] = ap[mt * 16 * A_STRIDE + 8 * A_STRIDE];
                a[mt][2] = ap[mt * 16 * A_STRIDE + 4];
                a[mt][3] = ap[mt * 16 * A_STRIDE + 8 * A_STRIDE + 4];
            }
            if (BLKN) {
                const uint32_t* bp = bpb_kn + kk * BKN_STRIDE;
                #pragma unroll
                for (int nt = 0; nt < 4; nt++) {
                    b[nt][0] = bp[nt * 8];
                    b[nt][1] = bp[4 * BKN_STRIDE + nt * 8];
                }
            } else {
                const uint32_t* bp = bpb_nk + kk;
                #pragma unroll
                for (int nt = 0; nt < 4; nt++) {
                    b[nt][0] = bp[nt * 8 * BNK_STRIDE];
                    b[nt][1] = bp[nt * 8 * BNK_STRIDE + 4];
                }
            }
            #pragma unroll
            for (int mt = 0; mt < 4; mt++)
                #pragma unroll
                for (int nt = 0; nt < 4; nt++)
                    mma_tf32(acc[mt][nt], a[mt], b[nt]);
        }
        __syncthreads();
    }

    // ---- epilogue ----
    #pragma unroll
    for (int mt = 0; mt < 4; mt++) {
        const int r0 = row0 + m0w + mt * 16 + r4;
        #pragma unroll
        for (int nt = 0; nt < 4; nt++) {
            const int col = col0 + n0w + nt * 8 + c4 * 2;
            float2 lo = make_float2(acc[mt][nt][0], acc[mt][nt][1]);
            float2 hi = make_float2(acc[mt][nt][2], acc[mt][nt][3]);
            if (EPI == 0) {
                // relu + bias, then PRE-ROUND to tf32 for downstream GEMMs
                float b0 = aux[col], b1 = aux[col + 1];
                lo.x = f2tf_f(fmaxf(lo.x + b0, 0.0f)); lo.y = f2tf_f(fmaxf(lo.y + b1, 0.0f));
                hi.x = f2tf_f(fmaxf(hi.x + b0, 0.0f)); hi.y = f2tf_f(fmaxf(hi.y + b1, 0.0f));
            } else if (EPI == 1) {
                float m0 = aux[col], m1 = aux[col + 1];
                lo.x = (m0 == 0.0f) ? NEGC : lo.x * 0.03125f;
                lo.y = (m1 == 0.0f) ? NEGC : lo.y * 0.03125f;
                hi.x = (m0 == 0.0f) ? NEGC : hi.x * 0.03125f;
                hi.y = (m1 == 0.0f) ? NEGC : hi.y * 0.03125f;
            } else {
                float2 rl = *reinterpret_cast<const float2*>(&res[(size_t)r0 * ldC + col]);
                float2 rh = *reinterpret_cast<const float2*>(&res[(size_t)(r0 + 8) * ldC + col]);
                lo.x += rl.x; lo.y += rl.y;
                hi.x += rh.x; hi.y += rh.y;
            }
            *reinterpret_cast<float2*>(&C[(size_t)r0 * ldC + col]) = lo;
            *reinterpret_cast<float2*>(&C[(size_t)(r0 + 8) * ldC + col]) = hi;
        }
    }
}

// ---------------------------------------------------------------------------
// softmax + query-mask; writes tf32-rounded attn (it feeds the next GEMM)
// ---------------------------------------------------------------------------
__global__ __launch_bounds__(256) void softmax_kernel() {
    const int r = blockIdx.x;
    const int b = r >> 11, qi = r & 2047;
    float* srow = g_sc + (size_t)b * SS * SS + (size_t)qi * SS;
    const float mq = g_mask[r];
    const int t = threadIdx.x;
    float loc[8];
    #pragma unroll
    for (int i = 0; i < 8; i++) loc[i] = srow[t + i * 256];
    float m = loc[0];
    #pragma unroll
    for (int i = 1; i < 8; i++) m = fmaxf(m, loc[i]);
    #pragma unroll
    for (int o = 16; o > 0; o >>= 1) m = fmaxf(m, __shfl_xor_sync(0xffffffffu, m, o));
    __shared__ float red[8];
    const int w = t >> 5, l = t & 31;
    if (l == 0) red[w] = m;
    __syncthreads();
    float bm = red[0];
    #pragma unroll
    for (int i = 1; i < 8; i++) bm = fmaxf(bm, red[i]);
    __syncthreads();
    float s = 0.0f;
    #pragma unroll
    for (int i = 0; i < 8; i++) { loc[i] = expf(loc[i] - bm); s += loc[i]; }
    #pragma unroll
    for (int o = 16; o > 0; o >>= 1) s += __shfl_xor_sync(0xffffffffu, s, o);
    if (l == 0) red[w] = s;
    __syncthreads();
    float bs = 0.0f;
    #pragma unroll
    for (int i = 0; i < 8; i++) bs += red[i];
    const float inv = mq / bs;
    #pragma unroll
    for (int i = 0; i < 8; i++) srow[t + i * 256] = f2tf_f(loc[i] * inv);
}

// ---------------------------------------------------------------------------
extern "C" void kernel_launch(void* const* d_in, const int* in_sizes, int n_in,
                              void* d_out, int out_size)
{
    const float* x  = (const float*)d_in[0];
    const float* Wq = (const float*)d_in[1];
    const float* bq = (const float*)d_in[2];
    const float* Wk = (const float*)d_in[3];
    const float* bk = (const float*)d_in[4];
    const float* Wv = (const float*)d_in[5];
    const float* bv = (const float*)d_in[6];
    float* out = (float*)d_out;

    float *xt, *wt, *q, *k, *v, *sc, *mask;
    cudaGetSymbolAddress((void**)&xt,   g_x);
    cudaGetSymbolAddress((void**)&wt,   g_w);
    cudaGetSymbolAddress((void**)&q,    g_q);
    cudaGetSymbolAddress((void**)&k,    g_k);
    cudaGetSymbolAddress((void**)&v,    g_v);
    cudaGetSymbolAddress((void**)&sc,   g_sc);
    cudaGetSymbolAddress((void**)&mask, g_mask);

    cudaFuncSetAttribute(tc_gemm<0, 1>, cudaFuncAttributeMaxDynamicSharedMemorySize, SMEM_TOTAL);
    cudaFuncSetAttribute(tc_gemm<1, 0>, cudaFuncAttributeMaxDynamicSharedMemorySize, SMEM_TOTAL);
    cudaFuncSetAttribute(tc_gemm<2, 1>, cudaFuncAttributeMaxDynamicSharedMemorySize, SMEM_TOTAL);

    const int M = BB * SS;                    // 16384
    const long long SD  = (long long)SS * DD;
    const long long SS2 = (long long)SS * SS;

    // 0) tf32 pre-rounding of x and weights
    cvt_tf32_kernel<<<592, 256>>>(x, xt, (int)((size_t)BB * SS * DD / 4));
    cvt_tf32_kernel<<<148, 256>>>(Wq, wt + 0 * (size_t)DD * DD, DD * DD / 4);
    cvt_tf32_kernel<<<148, 256>>>(Wk, wt + 1 * (size_t)DD * DD, DD * DD / 4);
    cvt_tf32_kernel<<<148, 256>>>(Wv, wt + 2 * (size_t)DD * DD, DD * DD / 4);

    // 1) masks (from original x)
    mask_kernel<<<M, 256>>>(x);

    // 2) QKV projections (outputs tf32-rounded)
    {
        dim3 grd(DD / 128, M / 128, 1);
        tc_gemm<0, 1><<<grd, 256, SMEM_TOTAL>>>(xt, wt + 0 * (size_t)DD * DD, bq, nullptr, q,
                                                DD, DD, DD, DD / 32, 0, 0, 0, 0, 0);
        tc_gemm<0, 1><<<grd, 256, SMEM_TOTAL>>>(xt, wt + 1 * (size_t)DD * DD, bk, nullptr, k,
                                                DD, DD, DD, DD / 32, 0, 0, 0, 0, 0);
        tc_gemm<0, 1><<<grd, 256, SMEM_TOTAL>>>(xt, wt + 2 * (size_t)DD * DD, bv, nullptr, v,
                                                DD, DD, DD, DD / 32, 0, 0, 0, 0, 0);
    }

    // 3) scores = q @ k^T / 32, key mask
    {
        dim3 grd(SS / 128, SS / 128, BB);
        tc_gemm<1, 0><<<grd, 256, SMEM_TOTAL>>>(q, k, mask, nullptr, sc,
                                                DD, DD, SS, DD / 32,
                                                SD, SD, SS2, SS, 0);
    }

    // 4) softmax + query mask (writes tf32-rounded attn)
    softmax_kernel<<<M, 256>>>();

    // 5) out = attn @ v + q
    {
        dim3 grd(DD / 128, SS / 128, BB);
        tc_gemm<2, 1><<<grd, 256, SMEM_TOTAL>>>(sc, v, nullptr, q, out,
                                                SS, DD, DD, SS / 32,
                                                SS2, SD, SD, 0, SD);
    }
}

// round 7
// speedup vs baseline: 6.1861x; 1.7910x over previous
#include <cuda_runtime.h>
#include <cuda_fp16.h>
#include <math.h>
#include <cstdint>

#define BB 8
#define SS 2048
#define DD 1024
#define NEGC (-4294967295.0f)   // -(2^32) + 1

// ---------------------------------------------------------------------------
// Scratch (__device__ globals)
// ---------------------------------------------------------------------------
__device__ __half g_xh [(size_t)BB * SS * DD];    // x  (half)
__device__ __half g_wh [(size_t)3 * DD * DD];     // W^T (half, [N][K])
__device__ __half g_qh [(size_t)BB * SS * DD];    // q (half; also residual)
__device__ __half g_kh [(size_t)BB * SS * DD];
__device__ __half g_vh [(size_t)BB * SS * DD];
__device__ __half g_vth[(size_t)BB * SS * DD];    // v^T per batch: [B][D][S]
__device__ __half g_at [(size_t)BB * SS * SS];    // attn (half)
__device__ float  g_sc [(size_t)BB * SS * SS];    // scores (fp32)
__device__ float  g_mask[(size_t)BB * SS];

// ---------------------------------------------------------------------------
// PTX helpers
// ---------------------------------------------------------------------------
#define CPA16(sa, gp) asm volatile("cp.async.cg.shared.global [%0], [%1], 16;" :: "r"(sa), "l"(gp))
#define CPA_COMMIT()  asm volatile("cp.async.commit_group;" ::: "memory")
template <int N>
__device__ __forceinline__ void cpa_wait() { asm volatile("cp.async.wait_group %0;" :: "n"(N) : "memory"); }

__device__ __forceinline__ uint32_t smem_u32(const void* p) {
    uint32_t a;
    asm("{ .reg .u64 t; cvta.to.shared.u64 t, %1; cvt.u32.u64 %0, t; }" : "=r"(a) : "l"(p));
    return a;
}
__device__ __forceinline__ void mma_f16(float* c, const uint32_t* a, const uint32_t* b) {
    asm volatile(
        "mma.sync.aligned.m16n8k16.row.col.f32.f16.f16.f32 "
        "{%0,%1,%2,%3}, {%4,%5,%6,%7}, {%8,%9}, {%0,%1,%2,%3};"
        : "+f"(c[0]), "+f"(c[1]), "+f"(c[2]), "+f"(c[3])
        : "r"(a[0]), "r"(a[1]), "r"(a[2]), "r"(a[3]), "r"(b[0]), "r"(b[1]));
}

// ---------------------------------------------------------------------------
// fp32 -> fp16 elementwise (x)
// ---------------------------------------------------------------------------
__global__ __launch_bounds__(256) void cvt_f2h(const float* __restrict__ src,
                                               __half* __restrict__ dst, int n4) {
    int i = blockIdx.x * 256 + threadIdx.x;
    int stride = gridDim.x * 256;
    __half2* d2 = (__half2*)dst;
    for (; i < n4; i += stride) {
        float4 v = reinterpret_cast<const float4*>(src)[i];
        d2[i * 2 + 0] = __floats2half2_rn(v.x, v.y);
        d2[i * 2 + 1] = __floats2half2_rn(v.z, v.w);
    }
}

// ---------------------------------------------------------------------------
// W [K][N] fp32  ->  W^T [N][K] half
// ---------------------------------------------------------------------------
__global__ __launch_bounds__(256) void transpose_w_h(const float* __restrict__ wq,
                                                     const float* __restrict__ wk,
                                                     const float* __restrict__ wv) {
    __shared__ float t[32][33];
    const float* src = (blockIdx.z == 0) ? wq : (blockIdx.z == 1) ? wk : wv;
    __half* dst = g_wh + (size_t)blockIdx.z * DD * DD;
    int f0 = blockIdx.x * 32, d0 = blockIdx.y * 32;
    #pragma unroll
    for (int i = threadIdx.y; i < 32; i += 8)
        t[i][threadIdx.x] = src[(size_t)(d0 + i) * DD + f0 + threadIdx.x];
    __syncthreads();
    #pragma unroll
    for (int i = threadIdx.y; i < 32; i += 8)
        dst[(size_t)(f0 + i) * DD + d0 + threadIdx.x] = __float2half_rn(t[threadIdx.x][i]);
}

// ---------------------------------------------------------------------------
// v [b][s][d] half -> vt [b][d][s] half
// ---------------------------------------------------------------------------
__global__ __launch_bounds__(256) void transpose_v_h() {
    __shared__ __half t[32][34];
    int b = blockIdx.z;
    int d0 = blockIdx.x * 32, s0 = blockIdx.y * 32;
    const __half* vb = g_vh + (size_t)b * SS * DD;
    __half* vtb = g_vth + (size_t)b * SS * DD;
    #pragma unroll
    for (int i = threadIdx.y; i < 32; i += 8)
        t[i][threadIdx.x] = vb[(size_t)(s0 + i) * DD + d0 + threadIdx.x];
    __syncthreads();
    #pragma unroll
    for (int i = threadIdx.y; i < 32; i += 8)
        vtb[(size_t)(d0 + i) * SS + s0 + threadIdx.x] = t[threadIdx.x][i];
}

// ---------------------------------------------------------------------------
// masks[b,s] = sin(|sum_d x|)  (from original fp32 x)
// ---------------------------------------------------------------------------
__global__ __launch_bounds__(256) void mask_kernel(const float* __restrict__ x) {
    int row = blockIdx.x;
    const float* xr = x + (size_t)row * DD;
    float s = 0.0f;
    for (int i = threadIdx.x; i < DD; i += 256) s += xr[i];
    #pragma unroll
    for (int o = 16; o > 0; o >>= 1) s += __shfl_xor_sync(0xffffffffu, s, o);
    __shared__ float ws[8];
    int w = threadIdx.x >> 5, l = threadIdx.x & 31;
    if (l == 0) ws[w] = s;
    __syncthreads();
    if (threadIdx.x == 0) {
        float t = 0.0f;
        #pragma unroll
        for (int i = 0; i < 8; i++) t += ws[i];
        g_mask[row] = (float)sin((double)fabsf(t));
    }
}

// ---------------------------------------------------------------------------
// fp16 tensor-core GEMM: C = A[M][K] * B[N][K]^T, both half, k-major.
// BM=BN=128, BK=64; 256 thr = 8 warps (2x4); warp tile 64x32; m16n8k16.
// EPI 0: half(relu(acc+bias)) -> half C
// EPI 1: acc/32 + key mask    -> fp32 C
// EPI 2: acc + res(half)      -> fp32 C
// ---------------------------------------------------------------------------
#define TS_H   72                               // halves per smem row (64 + 8 pad)
#define TS_U   36                               // uint32 per smem row
#define T_BYTES (128 * TS_H * 2)                // 18432
#define STAGE_BYTES (2 * T_BYTES)               // 36864
#define SMEM_TOTAL  (2 * STAGE_BYTES)           // 73728

__device__ __forceinline__ void load_h(uint32_t s, const __half* __restrict__ g,
                                       int ld, int tid) {
    // 128 rows x 64 halves = 1024 x 16B chunks, 4 per thread
    #pragma unroll
    for (int i = 0; i < 4; i++) {
        int idx = tid + i * 256;
        int row = idx >> 3, c = idx & 7;
        CPA16(s + (uint32_t)(row * TS_H + c * 8) * 2, g + (size_t)row * ld + c * 8);
    }
}

template <int EPI>
__global__ __launch_bounds__(256, 2)
void hgemm(const __half* __restrict__ A, const __half* __restrict__ B,
           const float* __restrict__ aux, const __half* __restrict__ res, void* Cv,
           int ldA, int ldB, int ldC, int KITER,
           long long sA, long long sB, long long sC, long long sAux, long long sRes)
{
    extern __shared__ char smem[];
    const uint32_t sb0 = smem_u32(smem);
    const int tid = threadIdx.x;
    const int wid = tid >> 5, lane = tid & 31;
    const int r4 = lane >> 2, c4 = lane & 3;
    const int wm = wid >> 2, wn = wid & 3;
    const int m0w = wm * 64, n0w = wn * 32;

    const int bz = blockIdx.z;
    A += (size_t)bz * sA;
    B += (size_t)bz * sB;
    if (EPI == 1) aux += (size_t)bz * sAux;
    if (EPI == 2) res += (size_t)bz * sRes;

    const int row0 = blockIdx.y * 128;
    const int col0 = blockIdx.x * 128;

    const __half* Ab = A + (size_t)row0 * ldA;
    const __half* Bb = B + (size_t)col0 * ldB;

    float acc[4][4][4];
    #pragma unroll
    for (int i = 0; i < 4; i++)
        #pragma unroll
        for (int j = 0; j < 4; j++)
            #pragma unroll
            for (int t = 0; t < 4; t++) acc[i][j][t] = 0.0f;

    load_h(sb0, Ab, ldA, tid);
    load_h(sb0 + T_BYTES, Bb, ldB, tid);
    CPA_COMMIT();

    for (int it = 0; it < KITER; it++) {
        if (it + 1 < KITER) {
            uint32_t sn = sb0 + ((it + 1) & 1) * STAGE_BYTES;
            load_h(sn, Ab + (it + 1) * 64, ldA, tid);
            load_h(sn + T_BYTES, Bb + (size_t)(it + 1) * 64, ldB, tid);
            CPA_COMMIT();
            cpa_wait<1>();
        } else {
            cpa_wait<0>();
        }
        __syncthreads();

        const uint32_t* As32 = (const uint32_t*)(smem + (it & 1) * STAGE_BYTES);
        const uint32_t* Bs32 = (const uint32_t*)(smem + (it & 1) * STAGE_BYTES + T_BYTES);
        const uint32_t* apb = As32 + (m0w + r4) * TS_U + c4;
        const uint32_t* bpb = Bs32 + (n0w + r4) * TS_U + c4;

        #pragma unroll
        for (int k2 = 0; k2 < 32; k2 += 8) {      // 4 k16-steps (uint32 offsets)
            uint32_t a[4][4], b[4][2];
            #pragma unroll
            for (int mt = 0; mt < 4; mt++) {
                const uint32_t* ap = apb + mt * 16 * TS_U + k2;
                a[mt][0] = ap[0];
                a[mt][1] = ap[8 * TS_U];
                a[mt][2] = ap[4];
                a[mt][3] = ap[8 * TS_U + 4];
            }
            #pragma unroll
            for (int nt = 0; nt < 4; nt++) {
                const uint32_t* bp = bpb + nt * 8 * TS_U + k2;
                b[nt][0] = bp[0];
                b[nt][1] = bp[4];
            }
            #pragma unroll
            for (int mt = 0; mt < 4; mt++)
                #pragma unroll
                for (int nt = 0; nt < 4; nt++)
                    mma_f16(acc[mt][nt], a[mt], b[nt]);
        }
        __syncthreads();
    }

    // ---- epilogue ----
    #pragma unroll
    for (int mt = 0; mt < 4; mt++) {
        const int r0 = row0 + m0w + mt * 16 + r4;
        #pragma unroll
        for (int nt = 0; nt < 4; nt++) {
            const int col = col0 + n0w + nt * 8 + c4 * 2;
            float2 lo = make_float2(acc[mt][nt][0], acc[mt][nt][1]);   // row r0
            float2 hi = make_float2(acc[mt][nt][2], acc[mt][nt][3]);   // row r0+8
            if (EPI == 0) {
                __half* Ch = (__half*)Cv;
                float b0 = aux[col], b1 = aux[col + 1];
                __half2 ol = __floats2half2_rn(fmaxf(lo.x + b0, 0.0f), fmaxf(lo.y + b1, 0.0f));
                __half2 oh = __floats2half2_rn(fmaxf(hi.x + b0, 0.0f), fmaxf(hi.y + b1, 0.0f));
                *reinterpret_cast<__half2*>(&Ch[(size_t)r0 * ldC + col]) = ol;
                *reinterpret_cast<__half2*>(&Ch[(size_t)(r0 + 8) * ldC + col]) = oh;
            } else if (EPI == 1) {
                float* Cf = (float*)Cv + (size_t)bz * sC;
                float m0 = aux[col], m1 = aux[col + 1];
                lo.x = (m0 == 0.0f) ? NEGC : lo.x * 0.03125f;
                lo.y = (m1 == 0.0f) ? NEGC : lo.y * 0.03125f;
                hi.x = (m0 == 0.0f) ? NEGC : hi.x * 0.03125f;
                hi.y = (m1 == 0.0f) ? NEGC : hi.y * 0.03125f;
                *reinterpret_cast<float2*>(&Cf[(size_t)r0 * ldC + col]) = lo;
                *reinterpret_cast<float2*>(&Cf[(size_t)(r0 + 8) * ldC + col]) = hi;
            } else {
                float* Cf = (float*)Cv + (size_t)bz * sC;
                __half2 rl = *reinterpret_cast<const __half2*>(&res[(size_t)r0 * ldC + col]);
                __half2 rh = *reinterpret_cast<const __half2*>(&res[(size_t)(r0 + 8) * ldC + col]);
                lo.x += __low2float(rl);  lo.y += __high2float(rl);
                hi.x += __low2float(rh);  hi.y += __high2float(rh);
                *reinterpret_cast<float2*>(&Cf[(size_t)r0 * ldC + col]) = lo;
                *reinterpret_cast<float2*>(&Cf[(size_t)(r0 + 8) * ldC + col]) = hi;
            }
        }
    }
}

// ---------------------------------------------------------------------------
// softmax + query-mask; fp32 scores in, half attn out
// ---------------------------------------------------------------------------
__global__ __launch_bounds__(256) void softmax_kernel() {
    const int r = blockIdx.x;
    const int b = r >> 11, qi = r & 2047;
    const float* srow = g_sc + (size_t)b * SS * SS + (size_t)qi * SS;
    __half* arow = g_at + (size_t)b * SS * SS + (size_t)qi * SS;
    const float mq = g_mask[r];
    const int t = threadIdx.x;
    float loc[8];
    #pragma unroll
    for (int i = 0; i < 8; i++) loc[i] = srow[t + i * 256];
    float m = loc[0];
    #pragma unroll
    for (int i = 1; i < 8; i++) m = fmaxf(m, loc[i]);
    #pragma unroll
    for (int o = 16; o > 0; o >>= 1) m = fmaxf(m, __shfl_xor_sync(0xffffffffu, m, o));
    __shared__ float red[8];
    const int w = t >> 5, l = t & 31;
    if (l == 0) red[w] = m;
    __syncthreads();
    float bm = red[0];
    #pragma unroll
    for (int i = 1; i < 8; i++) bm = fmaxf(bm, red[i]);
    __syncthreads();
    float s = 0.0f;
    #pragma unroll
    for (int i = 0; i < 8; i++) { loc[i] = expf(loc[i] - bm); s += loc[i]; }
    #pragma unroll
    for (int o = 16; o > 0; o >>= 1) s += __shfl_xor_sync(0xffffffffu, s, o);
    if (l == 0) red[w] = s;
    __syncthreads();
    float bs = 0.0f;
    #pragma unroll
    for (int i = 0; i < 8; i++) bs += red[i];
    const float inv = mq / bs;
    #pragma unroll
    for (int i = 0; i < 8; i++) arow[t + i * 256] = __float2half_rn(loc[i] * inv);
}

// ---------------------------------------------------------------------------
extern "C" void kernel_launch(void* const* d_in, const int* in_sizes, int n_in,
                              void* d_out, int out_size)
{
    const float* x  = (const float*)d_in[0];
    const float* Wq = (const float*)d_in[1];
    const float* bq = (const float*)d_in[2];
    const float* Wk = (const float*)d_in[3];
    const float* bk = (const float*)d_in[4];
    const float* Wv = (const float*)d_in[5];
    const float* bv = (const float*)d_in[6];
    float* out = (float*)d_out;

    __half *xh, *wh, *qh, *kh, *vh, *vth, *at;
    float *sc, *mask;
    cudaGetSymbolAddress((void**)&xh,   g_xh);
    cudaGetSymbolAddress((void**)&wh,   g_wh);
    cudaGetSymbolAddress((void**)&qh,   g_qh);
    cudaGetSymbolAddress((void**)&kh,   g_kh);
    cudaGetSymbolAddress((void**)&vh,   g_vh);
    cudaGetSymbolAddress((void**)&vth,  g_vth);
    cudaGetSymbolAddress((void**)&at,   g_at);
    cudaGetSymbolAddress((void**)&sc,   g_sc);
    cudaGetSymbolAddress((void**)&mask, g_mask);

    cudaFuncSetAttribute(hgemm<0>, cudaFuncAttributeMaxDynamicSharedMemorySize, SMEM_TOTAL);
    cudaFuncSetAttribute(hgemm<1>, cudaFuncAttributeMaxDynamicSharedMemorySize, SMEM_TOTAL);
    cudaFuncSetAttribute(hgemm<2>, cudaFuncAttributeMaxDynamicSharedMemorySize, SMEM_TOTAL);

    const int M = BB * SS;                    // 16384
    const long long SD  = (long long)SS * DD;
    const long long SS2 = (long long)SS * SS;

    // 0) input conversions
    cvt_f2h<<<592, 256>>>(x, xh, (int)((size_t)BB * SS * DD / 4));
    transpose_w_h<<<dim3(32, 32, 3), dim3(32, 8)>>>(Wq, Wk, Wv);

    // 1) masks (from original fp32 x)
    mask_kernel<<<M, 256>>>(x);

    // 2) QKV projections -> half
    {
        dim3 grd(DD / 128, M / 128, 1);
        hgemm<0><<<grd, 256, SMEM_TOTAL>>>(xh, wh + 0 * (size_t)DD * DD, bq, nullptr, qh,
                                           DD, DD, DD, DD / 64, 0, 0, 0, 0, 0);
        hgemm<0><<<grd, 256, SMEM_TOTAL>>>(xh, wh + 1 * (size_t)DD * DD, bk, nullptr, kh,
                                           DD, DD, DD, DD / 64, 0, 0, 0, 0, 0);
        hgemm<0><<<grd, 256, SMEM_TOTAL>>>(xh, wh + 2 * (size_t)DD * DD, bv, nullptr, vh,
                                           DD, DD, DD, DD / 64, 0, 0, 0, 0, 0);
    }

    // 3) v -> v^T per batch
    transpose_v_h<<<dim3(DD / 32, SS / 32, BB), dim3(32, 8)>>>();

    // 4) scores = q @ k^T / 32 + key mask -> fp32
    {
        dim3 grd(SS / 128, SS / 128, BB);
        hgemm<1><<<grd, 256, SMEM_TOTAL>>>(qh, kh, mask, nullptr, sc,
                                           DD, DD, SS, DD / 64,
                                           SD, SD, SS2, SS, 0);
    }

    // 5) softmax + query mask -> half attn
    softmax_kernel<<<M, 256>>>();

    // 6) out = attn @ v + q  (fp32 out)
    {
        dim3 grd(DD / 128, SS / 128, BB);
        hgemm<2><<<grd, 256, SMEM_TOTAL>>>(at, vth, nullptr, qh, out,
                                           SS, SS, DD, SS / 64,
                                           SS2, SD, SD, 0, SD);
    }
}